// round 10
// baseline (speedup 1.0000x reference)
#include <cuda_runtime.h>
#include <cstdint>

#define NHh 8
#define Dm 256          // NH*HD
#define OC 1280         // NH*(4*KD+HD)
#define HW 4096
#define NB 2
#define SCALEF 0.17677669529663687f
#define VF_PANEL 2240   // floats per V fragment panel (16 blocks x 140)

// Scratch (device globals; no runtime allocation allowed)
__device__ float P_g[NB * OC * HW];            // [b][o][hw]
__device__ float R_g[NB * NHh * 64 * HW];      // [b][H][i][hw] row softmax
__device__ float C_g[NB * NHh * 64 * HW];      // [b][H][j][hw] col softmax
__device__ float Vf_g[16 * 64 * VF_PANEL];     // tf32 V fragments [bh][i][panel]

// ---------------------------------------------------------------------------
// helpers
// ---------------------------------------------------------------------------
__device__ __forceinline__ uint32_t f2tf32(float x) {
    uint32_t u;
    asm("cvt.rna.tf32.f32 %0, %1;" : "=r"(u) : "f"(x));
    return u;
}
__device__ __forceinline__ float f2tf32f(float x) {
    uint32_t u = f2tf32(x);
    return __uint_as_float(u);
}
__device__ __forceinline__ void mma16n8k8(float* d, const uint32_t* a,
                                          uint32_t b0, uint32_t b1) {
    asm volatile("mma.sync.aligned.m16n8k8.row.col.f32.tf32.tf32.f32 "
                 "{%0,%1,%2,%3}, {%4,%5,%6,%7}, {%8,%9}, {%0,%1,%2,%3};"
                 : "+f"(d[0]), "+f"(d[1]), "+f"(d[2]), "+f"(d[3])
                 : "r"(a[0]), "r"(a[1]), "r"(a[2]), "r"(a[3]), "r"(b0), "r"(b1));
}
__device__ __forceinline__ void mma16n8k8_z(float* d, const uint32_t* a,
                                            uint32_t b0, uint32_t b1) {
    asm volatile("mma.sync.aligned.m16n8k8.row.col.f32.tf32.tf32.f32 "
                 "{%0,%1,%2,%3}, {%4,%5,%6,%7}, {%8,%9}, {%10,%10,%10,%10};"
                 : "=f"(d[0]), "=f"(d[1]), "=f"(d[2]), "=f"(d[3])
                 : "r"(a[0]), "r"(a[1]), "r"(a[2]), "r"(a[3]), "r"(b0), "r"(b1),
                   "f"(0.0f));
}
__device__ __forceinline__ uint32_t smem_u32(const void* p) {
    uint32_t a;
    asm("{ .reg .u64 t; cvta.to.shared.u64 t, %1; cvt.u32.u64 %0, t; }" : "=r"(a) : "l"(p));
    return a;
}
#define CP_ASYNC16(dst_u32, src_ptr) \
    asm volatile("cp.async.cg.shared.global [%0], [%1], 16;" :: "r"(dst_u32), "l"(src_ptr))
#define CP_COMMIT() asm volatile("cp.async.commit_group;" ::: "memory")
#define CP_WAIT2()  asm volatile("cp.async.wait_group 2;" ::: "memory")

// ---------------------------------------------------------------------------
// Kernel 1: projection GEMM (tf32 mma.sync)  (unchanged)
// ---------------------------------------------------------------------------
#define PJ_AS  (128 * 36)
#define PJ_BS  (32 * 136)
#define PJ_SMEM_FLOATS (2 * PJ_AS + 2 * PJ_BS)
#define PJ_SMEM_BYTES  (PJ_SMEM_FLOATS * 4)

__global__ void __launch_bounds__(256, 2) proj_mma(const float* __restrict__ x,
                                                   const float* __restrict__ w)
{
    extern __shared__ float sm[];
    float* as = sm;
    float* bs = sm + 2 * PJ_AS;

    const int b  = blockIdx.z;
    const int m0 = blockIdx.y * 128;
    const int n0 = blockIdx.x * 128;
    const int tid  = threadIdx.x;
    const int wid  = tid >> 5;
    const int lane = tid & 31;
    const int mrow = lane >> 2;
    const int kcol = lane & 3;
    const int wm = wid & 1;
    const int wn = wid >> 1;
    const float* xb = x + b * (Dm * HW);

    float acc[4][4][4] = {};
    float pa[16], pbr[16];

    #pragma unroll
    for (int q = 0; q < 16; q++) {
        int f = tid + q * 256;
        int o = f >> 5, c = f & 31;
        pa[q]  = w[(m0 + o) * Dm + c];
        int k = f >> 7, n = f & 127;
        pbr[q] = xb[k * HW + n0 + n];
    }
    #pragma unroll
    for (int q = 0; q < 16; q++) {
        int f = tid + q * 256;
        int o = f >> 5, c = f & 31;
        as[o * 36 + c] = f2tf32f(pa[q]);
        int k = f >> 7, n = f & 127;
        bs[k * 136 + n] = f2tf32f(pbr[q]);
    }

    for (int kt = 0; kt < 8; kt++) {
        __syncthreads();
        const int buf = kt & 1;
        if (kt < 7) {
            const int c0 = (kt + 1) * 32;
            #pragma unroll
            for (int q = 0; q < 16; q++) {
                int f = tid + q * 256;
                int o = f >> 5, c = f & 31;
                pa[q]  = w[(m0 + o) * Dm + c0 + c];
                int k = f >> 7, n = f & 127;
                pbr[q] = xb[(c0 + k) * HW + n0 + n];
            }
        }
        const float* ab = as + buf * PJ_AS;
        const float* bb = bs + buf * PJ_BS;
        #pragma unroll
        for (int k8 = 0; k8 < 4; k8++) {
            uint32_t a[4][4];
            #pragma unroll
            for (int msl = 0; msl < 4; msl++) {
                int r0 = wm * 64 + msl * 16 + mrow;
                a[msl][0] = __float_as_uint(ab[r0 * 36 + k8 * 8 + kcol]);
                a[msl][1] = __float_as_uint(ab[(r0 + 8) * 36 + k8 * 8 + kcol]);
                a[msl][2] = __float_as_uint(ab[r0 * 36 + k8 * 8 + 4 + kcol]);
                a[msl][3] = __float_as_uint(ab[(r0 + 8) * 36 + k8 * 8 + 4 + kcol]);
            }
            #pragma unroll
            for (int nsl = 0; nsl < 4; nsl++) {
                int ncol = wn * 32 + nsl * 8 + mrow;
                uint32_t b0 = __float_as_uint(bb[(k8 * 8 + kcol) * 136 + ncol]);
                uint32_t b1 = __float_as_uint(bb[(k8 * 8 + 4 + kcol) * 136 + ncol]);
                #pragma unroll
                for (int msl = 0; msl < 4; msl++)
                    mma16n8k8(acc[msl][nsl], a[msl], b0, b1);
            }
        }
        if (kt < 7) {
            float* an = as + (1 - buf) * PJ_AS;
            float* bn = bs + (1 - buf) * PJ_BS;
            #pragma unroll
            for (int q = 0; q < 16; q++) {
                int f = tid + q * 256;
                int o = f >> 5, c = f & 31;
                an[o * 36 + c] = f2tf32f(pa[q]);
                int k = f >> 7, n = f & 127;
                bn[k * 136 + n] = f2tf32f(pbr[q]);
            }
        }
    }

    float* pb = P_g + b * (OC * HW);
    #pragma unroll
    for (int msl = 0; msl < 4; msl++) {
        #pragma unroll
        for (int nsl = 0; nsl < 4; nsl++) {
            int r0 = m0 + wm * 64 + msl * 16 + mrow;
            int cn = n0 + wn * 32 + nsl * 8 + 2 * kcol;
            *(float2*)&pb[r0 * HW + cn] =
                make_float2(acc[msl][nsl][0], acc[msl][nsl][1]);
            *(float2*)&pb[(r0 + 8) * HW + cn] =
                make_float2(acc[msl][nsl][2], acc[msl][nsl][3]);
        }
    }
}

// ---------------------------------------------------------------------------
// Kernel 1.5: V fragment prep — convert V panels to tf32 fragment layout ONCE
// per (bh, i).  grid (64 i, 16 bh), 128 threads.
//   fragment: fb=(j>>3)*2+(d>>4), ln=(d&7)*4+(j&3), reg=((d>>3)&1)+2*((j>>2)&1)
// ---------------------------------------------------------------------------
__global__ void __launch_bounds__(128) vfrag_prep()
{
    __shared__ float fs[VF_PANEL];
    const int i  = blockIdx.x;
    const int bh = blockIdx.y;
    const int b  = bh >> 3, H = bh & 7;
    const float* vbase = P_g + (b * OC + H * 160 + 128) * HW;
    const int tid = threadIdx.x;

    #pragma unroll
    for (int q = 0; q < 16; q++) {
        int f = tid + q * 128;
        int d = f >> 6, j = f & 63;
        float val = f2tf32f(vbase[d * HW + i * 64 + j]);
        int fb  = (j >> 3) * 2 + (d >> 4);
        int ln  = (d & 7) * 4 + (j & 3);
        int reg = ((d >> 3) & 1) + 2 * ((j >> 2) & 1);
        fs[fb * 140 + ln * 4 + reg] = val;
    }
    __syncthreads();
    uint4* dst = (uint4*)(Vf_g + (bh * 64 + i) * VF_PANEL);
    const uint4* src = (const uint4*)fs;
    for (int t = tid; t < 560; t += 128) dst[t] = src[t];
}

// ---------------------------------------------------------------------------
// Kernel 2: row attention, w-quad version (unchanged)
// ---------------------------------------------------------------------------
#define QSTR (32 * 65 + 1)
#define ASTR (64 * 65 + 1)
#define RA_SMEM_FLOATS (8 * QSTR)
#define RA_SMEM_BYTES  (RA_SMEM_FLOATS * 4)

__global__ void __launch_bounds__(256) row_attn4()
{
    extern __shared__ float smb[];
    float* q_s = smb;
    float* k_s = smb + 4 * QSTR;

    const int w0 = blockIdx.x * 4;
    const int bh = blockIdx.y;
    const int b  = bh >> 3, H = bh & 7;
    const float* qb = P_g + (b * OC + H * 160) * HW;
    const float* kb = qb + 32 * HW;
    const int tid = threadIdx.x;

    for (int e = tid; e < 8192; e += 256) {
        int ww = e & 3, i = (e >> 2) & 63, d = e >> 8;
        q_s[ww * QSTR + d * 65 + i] = qb[d * HW + i * 64 + w0 + ww];
        k_s[ww * QSTR + d * 65 + i] = kb[d * HW + i * 64 + w0 + ww];
    }
    __syncthreads();

    const int ww = tid >> 6;
    const int gt = tid & 63;
    const int ti = (gt >> 3) * 8;
    const int tj = (gt & 7) * 8;
    const float* qq = q_s + ww * QSTR;
    const float* kk = k_s + ww * QSTR;

    float acc[8][8] = {};
    #pragma unroll 4
    for (int d = 0; d < 32; d++) {
        float qv[8], kv[8];
        #pragma unroll
        for (int u = 0; u < 8; u++) qv[u] = qq[d * 65 + ti + u];
        #pragma unroll
        for (int v = 0; v < 8; v++) kv[v] = kk[d * 65 + tj + v];
        #pragma unroll
        for (int u = 0; u < 8; u++)
            #pragma unroll
            for (int v = 0; v < 8; v++)
                acc[u][v] += qv[u] * kv[v];
    }
    __syncthreads();

    float* a_s = smb;
    #pragma unroll
    for (int u = 0; u < 8; u++)
        #pragma unroll
        for (int v = 0; v < 8; v++)
            a_s[ww * ASTR + (ti + u) * 65 + (tj + v)] = acc[u][v] * SCALEF;
    __syncthreads();

    {
        const int ww2 = tid & 3;
        const int j   = tid >> 2;
        float* col = a_s + ww2 * ASTR + j;
        float mx = -1e30f;
        #pragma unroll 8
        for (int i = 0; i < 64; i++) mx = fmaxf(mx, col[i * 65]);
        float s = 0.f;
        #pragma unroll 8
        for (int i = 0; i < 64; i++) {
            float e = __expf(col[i * 65] - mx);
            col[i * 65] = e;
            s += e;
        }
        float inv = 1.f / s;
        float* rb = R_g + bh * (64 * HW) + j * 64 + w0 + ww2;
        #pragma unroll 8
        for (int i = 0; i < 64; i++)
            rb[i * HW] = col[i * 65] * inv;
    }
}

// ---------------------------------------------------------------------------
// Kernel 3: column attention (unchanged)
// ---------------------------------------------------------------------------
__global__ void col_attn_kernel()
{
    int h  = blockIdx.x;
    int bh = blockIdx.y;
    int b  = bh >> 3, H = bh & 7;
    const float* base = P_g + (b * OC + H * 160) * HW;
    int tid = threadIdx.x;

    __shared__ float q_s[32][64];
    __shared__ float k_s[32][64];
    __shared__ float a_s[64][68];

    for (int f = tid; f < 2048; f += 256) {
        int d = f >> 6, i = f & 63;
        q_s[d][i] = base[(64 + d) * HW + h * 64 + i];
        k_s[d][i] = base[(96 + d) * HW + h * 64 + i];
    }
    __syncthreads();

    int ti = (tid >> 4) * 4;
    int tj = (tid & 15) * 4;
    float acc[4][4] = {};
    #pragma unroll
    for (int d = 0; d < 32; d++) {
        float4 av = *(const float4*)&q_s[d][ti];
        float4 bv = *(const float4*)&k_s[d][tj];
        float avv[4] = {av.x, av.y, av.z, av.w};
        float bvv[4] = {bv.x, bv.y, bv.z, bv.w};
        #pragma unroll
        for (int u = 0; u < 4; u++)
            #pragma unroll
            for (int v2 = 0; v2 < 4; v2++)
                acc[u][v2] += avv[u] * bvv[v2];
    }
    #pragma unroll
    for (int u = 0; u < 4; u++)
        #pragma unroll
        for (int v2 = 0; v2 < 4; v2++)
            a_s[ti + u][tj + v2] = acc[u][v2] * SCALEF;
    __syncthreads();

    if (tid < 64) {
        int j = tid;
        float mx = -1e30f;
        #pragma unroll 8
        for (int i = 0; i < 64; i++) mx = fmaxf(mx, a_s[i][j]);
        float s = 0.f;
        #pragma unroll 8
        for (int i = 0; i < 64; i++) {
            float e = __expf(a_s[i][j] - mx);
            a_s[i][j] = e;
            s += e;
        }
        float inv = 1.f / s;
        float* cb = C_g + bh * (64 * HW);
        #pragma unroll 8
        for (int i = 0; i < 64; i++)
            cb[i * HW + h * 64 + j] = a_s[i][j] * inv;
    }
}

// ---------------------------------------------------------------------------
// Kernel 4: fused output — c-fragments register-resident, V fragments
// streamed via cp.async from precomputed Vf_g.
// CTA: 256 threads / 8 warps / 128 hw tile.
// Warp = (msw = d-half) x (q = 32-hw quarter); ns=4, ms=1 per warp.
//   per i:  t = V_i(ms half) @ c(regs);  acc += r o t;   out = acc + v
// ---------------------------------------------------------------------------
#define FO_STAGES 4
#define FO_SMEM_BYTES (FO_STAGES * VF_PANEL * 4)   // 35840 B (c staging 33792 fits)

__global__ void __launch_bounds__(256) fused_out_mma(float* __restrict__ out)
{
    extern __shared__ float sm[];
    const int hw0 = blockIdx.x * 128;
    const int bh  = blockIdx.y;
    const int b   = bh >> 3, H = bh & 7;
    const float* vbase = P_g + (b * OC + H * 160 + 128) * HW;
    const float* rbase = R_g + bh * (64 * HW);
    const float* cbase = C_g + bh * (64 * HW);
    const int tid  = threadIdx.x;
    const int wid  = tid >> 5;
    const int lane = tid & 31;
    const int mrow = lane >> 2;   // 0..7
    const int kcol = lane & 3;    // 0..3
    const int msw  = wid >> 2;    // 0..1  (d half)
    const int q    = wid & 3;     // 0..3  (hw quarter)

    // Phase 1: stage c fragments into smem (scatter), then load to registers.
    for (int f = tid; f < 8192; f += 256) {
        int j = f >> 7, m = f & 127;
        int nb  = m >> 3;
        int jcp = j >> 4;
        int ln  = (m & 7) * 4 + (j & 3);
        int reg = ((j >> 3) & 1) * 2 + ((j >> 2) & 1);
        sm[(nb * 4 + jcp) * 132 + ln * 4 + reg] = f2tf32f(cbase[j * HW + hw0 + m]);
    }
    __syncthreads();
    uint4 cq[4][4];
    {
        const uint4* cf4 = (const uint4*)sm;
        #pragma unroll
        for (int ns = 0; ns < 4; ns++)
            #pragma unroll
            for (int jcp = 0; jcp < 4; jcp++)
                cq[ns][jcp] = cf4[((q * 4 + ns) * 4 + jcp) * 33 + lane];
    }
    __syncthreads();   // smem now reusable for A stages

    // Phase 2: i-loop with cp.async pipeline on V fragment panels.
    const float* vfg = Vf_g + bh * 64 * VF_PANEL;
    const uint32_t smbase = smem_u32(sm);

    // prologue: stages 0..2
    #pragma unroll
    for (int s = 0; s < FO_STAGES - 1; s++) {
        const float* src = vfg + s * VF_PANEL;
        uint32_t dst = smbase + s * (VF_PANEL * 4);
        for (int t = tid; t < 560; t += 256)
            CP_ASYNC16(dst + t * 16, src + t * 4);
        CP_COMMIT();
    }

    float acc[4][4] = {};
    for (int i = 0; i < 64; i++) {
        CP_WAIT2();
        __syncthreads();
        const uint4* vp4 = (const uint4*)(sm + (i & 3) * VF_PANEL);

        float t[4][4];
        #pragma unroll
        for (int jc = 0; jc < 8; jc++) {
            uint4 av = vp4[(jc * 2 + msw) * 35 + lane];
            uint32_t a[4] = {av.x, av.y, av.z, av.w};
            #pragma unroll
            for (int ns = 0; ns < 4; ns++) {
                uint32_t b0 = (jc & 1) ? cq[ns][jc >> 1].z : cq[ns][jc >> 1].x;
                uint32_t b1 = (jc & 1) ? cq[ns][jc >> 1].w : cq[ns][jc >> 1].y;
                if (jc == 0) mma16n8k8_z(t[ns], a, b0, b1);
                else         mma16n8k8(t[ns], a, b0, b1);
            }
        }
        // acc += r[i, col] * t   (fragment cols 2*kcol, 2*kcol+1)
        #pragma unroll
        for (int ns = 0; ns < 4; ns++) {
            int col0 = q * 32 + ns * 8 + 2 * kcol;
            float2 rv2 = __ldg((const float2*)&rbase[i * HW + hw0 + col0]);
            acc[ns][0] += rv2.x * t[ns][0];
            acc[ns][1] += rv2.y * t[ns][1];
            acc[ns][2] += rv2.x * t[ns][2];
            acc[ns][3] += rv2.y * t[ns][3];
        }
        // issue stage i+3
        if (i + FO_STAGES - 1 < 64) {
            const float* src = vfg + (i + FO_STAGES - 1) * VF_PANEL;
            uint32_t dst = smbase + ((i + FO_STAGES - 1) & 3) * (VF_PANEL * 4);
            for (int t2 = tid; t2 < 560; t2 += 256)
                CP_ASYNC16(dst + t2 * 16, src + t2 * 4);
        }
        CP_COMMIT();
    }

    // epilogue: out[d][hw] = acc + v
    const int d0 = msw * 16 + mrow;
    float* ob = out + (b * 256 + H * 32) * HW;
    #pragma unroll
    for (int ns = 0; ns < 4; ns++) {
        int col = hw0 + q * 32 + ns * 8 + 2 * kcol;
        float2 v0 = *(const float2*)&vbase[d0 * HW + col];
        float2 v1 = *(const float2*)&vbase[(d0 + 8) * HW + col];
        *(float2*)&ob[d0 * HW + col] =
            make_float2(acc[ns][0] + v0.x, acc[ns][1] + v0.y);
        *(float2*)&ob[(d0 + 8) * HW + col] =
            make_float2(acc[ns][2] + v1.x, acc[ns][3] + v1.y);
    }
}

// ---------------------------------------------------------------------------
extern "C" void kernel_launch(void* const* d_in, const int* in_sizes, int n_in,
                              void* d_out, int out_size)
{
    const float* x = (const float*)d_in[0];
    const float* w = (const float*)d_in[1];
    if (n_in >= 2 && in_sizes[0] == 327680 && in_sizes[1] == 2097152) {
        const float* t = x; x = w; w = t;
    }
    float* out = (float*)d_out;

    static int attr_set = 0;
    if (!attr_set) {
        cudaFuncSetAttribute(proj_mma, cudaFuncAttributeMaxDynamicSharedMemorySize,
                             PJ_SMEM_BYTES);
        cudaFuncSetAttribute(row_attn4, cudaFuncAttributeMaxDynamicSharedMemorySize,
                             RA_SMEM_BYTES);
        cudaFuncSetAttribute(fused_out_mma, cudaFuncAttributeMaxDynamicSharedMemorySize,
                             FO_SMEM_BYTES);
        attr_set = 1;
    }

    dim3 g1(32, 10, 2);
    proj_mma<<<g1, 256, PJ_SMEM_BYTES>>>(x, w);

    dim3 gp(64, 16);
    vfrag_prep<<<gp, 128>>>();

    dim3 g2r(16, 16);
    row_attn4<<<g2r, 256, RA_SMEM_BYTES>>>();
    dim3 g2c(64, 16);
    col_attn_kernel<<<g2c, 256>>>();

    dim3 g4(32, 16);
    fused_out_mma<<<g4, 256, FO_SMEM_BYTES>>>(out);
}

// round 13
// speedup vs baseline: 1.0342x; 1.0342x over previous
#include <cuda_runtime.h>
#include <cstdint>

#define NHh 8
#define Dm 256          // NH*HD
#define OC 1280         // NH*(4*KD+HD)
#define HW 4096
#define NB 2
#define SCALEF 0.17677669529663687f

// Scratch (device globals; no runtime allocation allowed)
__device__ float P_g[NB * OC * HW];            // [b][o][hw]
__device__ float R_g[NB * NHh * 64 * HW];      // [b][H][i][hw] row softmax
__device__ float C_g[NB * NHh * 64 * HW];      // [b][H][j][hw] col softmax

// ---------------------------------------------------------------------------
// helpers
// ---------------------------------------------------------------------------
__device__ __forceinline__ uint32_t f2tf32(float x) {
    uint32_t u;
    asm("cvt.rna.tf32.f32 %0, %1;" : "=r"(u) : "f"(x));
    return u;
}
__device__ __forceinline__ float f2tf32f(float x) {
    uint32_t u = f2tf32(x);
    return __uint_as_float(u);
}
__device__ __forceinline__ void mma16n8k8(float* d, const uint32_t* a,
                                          uint32_t b0, uint32_t b1) {
    asm volatile("mma.sync.aligned.m16n8k8.row.col.f32.tf32.tf32.f32 "
                 "{%0,%1,%2,%3}, {%4,%5,%6,%7}, {%8,%9}, {%0,%1,%2,%3};"
                 : "+f"(d[0]), "+f"(d[1]), "+f"(d[2]), "+f"(d[3])
                 : "r"(a[0]), "r"(a[1]), "r"(a[2]), "r"(a[3]), "r"(b0), "r"(b1));
}
__device__ __forceinline__ void mma16n8k8_z(float* d, const uint32_t* a,
                                            uint32_t b0, uint32_t b1) {
    asm volatile("mma.sync.aligned.m16n8k8.row.col.f32.tf32.tf32.f32 "
                 "{%0,%1,%2,%3}, {%4,%5,%6,%7}, {%8,%9}, {%10,%10,%10,%10};"
                 : "=f"(d[0]), "=f"(d[1]), "=f"(d[2]), "=f"(d[3])
                 : "r"(a[0]), "r"(a[1]), "r"(a[2]), "r"(a[3]), "r"(b0), "r"(b1),
                   "f"(0.0f));
}

// ---------------------------------------------------------------------------
// Kernel 1: projection GEMM (tf32 mma.sync) — fragment-layout smem.
//   P[b, m0+o, n0+s] = sum_c W[o][c] * X[b][c][s]
// CTA 128x128, K in 8 double-buffered ktiles of 32; 8 warps (2 wm x 4 wn).
// A fragments: block (wm*4+msl)*4+k8, 32 uint4/block (pitch 33) -> LDS.128.
// B fragments: block (wn*4+nsl)*4+k8, 32 uint2/block (pitch 33) -> LDS.64.
// ---------------------------------------------------------------------------
#define PJ_AF 4224      // floats per A buffer (32 blocks x 33 uint4)
#define PJ_BF 4224      // floats per B buffer (64 blocks x 33 uint2)
#define PJ_SMEM_FLOATS (2 * PJ_AF + 2 * PJ_BF)
#define PJ_SMEM_BYTES  (PJ_SMEM_FLOATS * 4)    // 67584 B

__global__ void __launch_bounds__(256) proj_mma(const float* __restrict__ x,
                                                const float* __restrict__ w)
{
    extern __shared__ float sm[];
    float* as = sm;                  // [2][PJ_AF]
    float* bs = sm + 2 * PJ_AF;      // [2][PJ_BF]

    const int b  = blockIdx.z;
    const int m0 = blockIdx.y * 128;
    const int n0 = blockIdx.x * 128;
    const int tid  = threadIdx.x;
    const int wid  = tid >> 5;
    const int lane = tid & 31;
    const int mrow = lane >> 2;
    const int kcol = lane & 3;
    const int wm = wid & 1;
    const int wn = wid >> 1;
    const float* xb = x + b * (Dm * HW);

    float acc[4][4][4] = {};
    float pa[16], pbr[16];

    // staging index helpers (computed per element)
    //   A elem (o,c): wm=o>>6, msl=(o>>4)&3, rlo=(o>>3)&1, mr=o&7
    //                 k8=c>>3, rhi=(c>>2)&1, kc=c&3
    //   idx = ((wm*4+msl)*4+k8)*132 + (mr*4+kc)*4 + rhi*2 + rlo
    //   B elem (k,n): k8=k>>3, kh=(k>>2)&1, kc=k&3; wn=n>>5, nsl=(n>>3)&3, mr=n&7
    //   idx = ((wn*4+nsl)*4+k8)*66 + (mr*4+kc)*2 + kh

    // prefetch + stage ktile 0
    #pragma unroll
    for (int q = 0; q < 16; q++) {
        int f = tid + q * 256;
        int o = f >> 5, c = f & 31;
        pa[q]  = w[(m0 + o) * Dm + c];
        int k = f >> 7, n = f & 127;
        pbr[q] = xb[k * HW + n0 + n];
    }
    #pragma unroll
    for (int q = 0; q < 16; q++) {
        int f = tid + q * 256;
        {
            int o = f >> 5, c = f & 31;
            int idx = (((o >> 6) * 4 + ((o >> 4) & 3)) * 4 + (c >> 3)) * 132
                    + ((o & 7) * 4 + (c & 3)) * 4 + ((c >> 2) & 1) * 2 + ((o >> 3) & 1);
            as[idx] = f2tf32f(pa[q]);
        }
        {
            int k = f >> 7, n = f & 127;
            int idx = (((n >> 5) * 4 + ((n >> 3) & 3)) * 4 + (k >> 3)) * 66
                    + ((n & 7) * 4 + (k & 3)) * 2 + ((k >> 2) & 1);
            bs[idx] = f2tf32f(pbr[q]);
        }
    }

    for (int kt = 0; kt < 8; kt++) {
        __syncthreads();
        const int buf = kt & 1;
        if (kt < 7) {
            const int c0 = (kt + 1) * 32;
            #pragma unroll
            for (int q = 0; q < 16; q++) {
                int f = tid + q * 256;
                int o = f >> 5, c = f & 31;
                pa[q]  = w[(m0 + o) * Dm + c0 + c];
                int k = f >> 7, n = f & 127;
                pbr[q] = xb[(c0 + k) * HW + n0 + n];
            }
        }
        const uint4* af4 = (const uint4*)(as + buf * PJ_AF);
        const uint2* bf2 = (const uint2*)(bs + buf * PJ_BF);
        #pragma unroll
        for (int k8 = 0; k8 < 4; k8++) {
            uint4 av[4];
            #pragma unroll
            for (int msl = 0; msl < 4; msl++)
                av[msl] = af4[((wm * 4 + msl) * 4 + k8) * 33 + lane];
            #pragma unroll
            for (int nsl = 0; nsl < 4; nsl++) {
                uint2 bv = bf2[((wn * 4 + nsl) * 4 + k8) * 33 + lane];
                #pragma unroll
                for (int msl = 0; msl < 4; msl++)
                    mma16n8k8(acc[msl][nsl], (const uint32_t*)&av[msl], bv.x, bv.y);
            }
        }
        if (kt < 7) {
            float* an = as + (1 - buf) * PJ_AF;
            float* bn = bs + (1 - buf) * PJ_BF;
            #pragma unroll
            for (int q = 0; q < 16; q++) {
                int f = tid + q * 256;
                {
                    int o = f >> 5, c = f & 31;
                    int idx = (((o >> 6) * 4 + ((o >> 4) & 3)) * 4 + (c >> 3)) * 132
                            + ((o & 7) * 4 + (c & 3)) * 4 + ((c >> 2) & 1) * 2 + ((o >> 3) & 1);
                    an[idx] = f2tf32f(pa[q]);
                }
                {
                    int k = f >> 7, n = f & 127;
                    int idx = (((n >> 5) * 4 + ((n >> 3) & 3)) * 4 + (k >> 3)) * 66
                            + ((n & 7) * 4 + (k & 3)) * 2 + ((k >> 2) & 1);
                    bn[idx] = f2tf32f(pbr[q]);
                }
            }
        }
    }

    float* pb = P_g + b * (OC * HW);
    #pragma unroll
    for (int msl = 0; msl < 4; msl++) {
        #pragma unroll
        for (int nsl = 0; nsl < 4; nsl++) {
            int r0 = m0 + wm * 64 + msl * 16 + mrow;
            int cn = n0 + wn * 32 + nsl * 8 + 2 * kcol;
            *(float2*)&pb[r0 * HW + cn] =
                make_float2(acc[msl][nsl][0], acc[msl][nsl][1]);
            *(float2*)&pb[(r0 + 8) * HW + cn] =
                make_float2(acc[msl][nsl][2], acc[msl][nsl][3]);
        }
    }
}

// ---------------------------------------------------------------------------
// Kernel 2: row attention, w-quad version (unchanged from R9)
// ---------------------------------------------------------------------------
#define QSTR (32 * 65 + 1)
#define ASTR (64 * 65 + 1)
#define RA_SMEM_FLOATS (8 * QSTR)
#define RA_SMEM_BYTES  (RA_SMEM_FLOATS * 4)

__global__ void __launch_bounds__(256) row_attn4()
{
    extern __shared__ float smb[];
    float* q_s = smb;
    float* k_s = smb + 4 * QSTR;

    const int w0 = blockIdx.x * 4;
    const int bh = blockIdx.y;
    const int b  = bh >> 3, H = bh & 7;
    const float* qb = P_g + (b * OC + H * 160) * HW;
    const float* kb = qb + 32 * HW;
    const int tid = threadIdx.x;

    for (int e = tid; e < 8192; e += 256) {
        int ww = e & 3, i = (e >> 2) & 63, d = e >> 8;
        q_s[ww * QSTR + d * 65 + i] = qb[d * HW + i * 64 + w0 + ww];
        k_s[ww * QSTR + d * 65 + i] = kb[d * HW + i * 64 + w0 + ww];
    }
    __syncthreads();

    const int ww = tid >> 6;
    const int gt = tid & 63;
    const int ti = (gt >> 3) * 8;
    const int tj = (gt & 7) * 8;
    const float* qq = q_s + ww * QSTR;
    const float* kk = k_s + ww * QSTR;

    float acc[8][8] = {};
    #pragma unroll 4
    for (int d = 0; d < 32; d++) {
        float qv[8], kv[8];
        #pragma unroll
        for (int u = 0; u < 8; u++) qv[u] = qq[d * 65 + ti + u];
        #pragma unroll
        for (int v = 0; v < 8; v++) kv[v] = kk[d * 65 + tj + v];
        #pragma unroll
        for (int u = 0; u < 8; u++)
            #pragma unroll
            for (int v = 0; v < 8; v++)
                acc[u][v] += qv[u] * kv[v];
    }
    __syncthreads();

    float* a_s = smb;
    #pragma unroll
    for (int u = 0; u < 8; u++)
        #pragma unroll
        for (int v = 0; v < 8; v++)
            a_s[ww * ASTR + (ti + u) * 65 + (tj + v)] = acc[u][v] * SCALEF;
    __syncthreads();

    {
        const int ww2 = tid & 3;
        const int j   = tid >> 2;
        float* col = a_s + ww2 * ASTR + j;
        float mx = -1e30f;
        #pragma unroll 8
        for (int i = 0; i < 64; i++) mx = fmaxf(mx, col[i * 65]);
        float s = 0.f;
        #pragma unroll 8
        for (int i = 0; i < 64; i++) {
            float e = __expf(col[i * 65] - mx);
            col[i * 65] = e;
            s += e;
        }
        float inv = 1.f / s;
        float* rb = R_g + bh * (64 * HW) + j * 64 + w0 + ww2;
        #pragma unroll 8
        for (int i = 0; i < 64; i++)
            rb[i * HW] = col[i * 65] * inv;
    }
}

// ---------------------------------------------------------------------------
// Kernel 3: column attention — parallel softmax (4 threads per column).
// ---------------------------------------------------------------------------
__global__ void col_attn_kernel()
{
    int h  = blockIdx.x;
    int bh = blockIdx.y;
    int b  = bh >> 3, H = bh & 7;
    const float* base = P_g + (b * OC + H * 160) * HW;
    int tid = threadIdx.x;

    __shared__ float q_s[32][64];
    __shared__ float k_s[32][64];
    __shared__ float a_s[64][68];

    for (int f = tid; f < 2048; f += 256) {
        int d = f >> 6, i = f & 63;
        q_s[d][i] = base[(64 + d) * HW + h * 64 + i];
        k_s[d][i] = base[(96 + d) * HW + h * 64 + i];
    }
    __syncthreads();

    int ti = (tid >> 4) * 4;
    int tj = (tid & 15) * 4;
    float acc[4][4] = {};
    #pragma unroll
    for (int d = 0; d < 32; d++) {
        float4 av = *(const float4*)&q_s[d][ti];
        float4 bv = *(const float4*)&k_s[d][tj];
        float avv[4] = {av.x, av.y, av.z, av.w};
        float bvv[4] = {bv.x, bv.y, bv.z, bv.w};
        #pragma unroll
        for (int u = 0; u < 4; u++)
            #pragma unroll
            for (int v2 = 0; v2 < 4; v2++)
                acc[u][v2] += avv[u] * bvv[v2];
    }
    #pragma unroll
    for (int u = 0; u < 4; u++)
        #pragma unroll
        for (int v2 = 0; v2 < 4; v2++)
            a_s[ti + u][tj + v2] = acc[u][v2] * SCALEF;
    __syncthreads();

    // parallel softmax over i: thread = (j, p); p covers 16 rows
    {
        float* pm = (float*)q_s;            // reuse: pm[4*65], ps[4*65]
        float* ps = pm + 4 * 65;
        const int j = tid & 63;
        const int p = tid >> 6;
        float mx = -1e30f;
        #pragma unroll
        for (int u = 0; u < 16; u++) mx = fmaxf(mx, a_s[p * 16 + u][j]);
        pm[p * 65 + j] = mx;
        __syncthreads();
        float m4 = fmaxf(fmaxf(pm[j], pm[65 + j]), fmaxf(pm[130 + j], pm[195 + j]));
        float s = 0.f;
        #pragma unroll
        for (int u = 0; u < 16; u++) {
            float e = __expf(a_s[p * 16 + u][j] - m4);
            a_s[p * 16 + u][j] = e;
            s += e;
        }
        ps[p * 65 + j] = s;
        __syncthreads();
        float tot = ps[j] + ps[65 + j] + ps[130 + j] + ps[195 + j];
        float inv = 1.f / tot;
        float* cb = C_g + bh * (64 * HW) + h * 64 + j;
        #pragma unroll
        for (int u = 0; u < 16; u++)
            cb[(p * 16 + u) * HW] = a_s[p * 16 + u][j] * inv;
    }
}

// ---------------------------------------------------------------------------
// Kernel 4: fused output — EXACT R9 version (117.8us proven).
// Wide warps (64 hw per warp); CTA 128 threads / 4 warps / 256 hw tile.
// ---------------------------------------------------------------------------
#define FO_CF   (128 * 132)
#define FO_VF   (16 * 140)
#define FO_RS   256
#define FO_SMEM_FLOATS (FO_CF + 2 * FO_VF + 2 * FO_RS)
#define FO_SMEM_BYTES  (FO_SMEM_FLOATS * 4)   // 87552 B -> 2 CTA/SM

__global__ void __launch_bounds__(128, 2) fused_out_mma(float* __restrict__ out)
{
    extern __shared__ float sm[];
    float* cf = sm;
    float* Vf = sm + FO_CF;
    float* rs = sm + FO_CF + 2 * FO_VF;

    const int hw0 = blockIdx.x * 256;
    const int bh  = blockIdx.y;
    const int b   = bh >> 3, H = bh & 7;
    const float* vbase = P_g + (b * OC + H * 160 + 128) * HW;
    const float* rbase = R_g + bh * (64 * HW);
    const float* cbase = C_g + bh * (64 * HW);
    const int tid  = threadIdx.x;
    const int wid  = tid >> 5;
    const int lane = tid & 31;
    const int mrow = lane >> 2;
    const int kcol = lane & 3;

    for (int f = tid; f < 16384; f += 128) {
        int j = f >> 8, m = f & 255;
        int nb   = m >> 3;
        int jcp  = j >> 4;
        int ln   = (m & 7) * 4 + (j & 3);
        int reg  = ((j >> 3) & 1) * 2 + ((j >> 2) & 1);
        cf[(nb * 4 + jcp) * 132 + ln * 4 + reg] = f2tf32f(cbase[j * HW + hw0 + m]);
    }
    #pragma unroll
    for (int q = 0; q < 16; q++) {
        int f = tid + q * 128;
        int d = f >> 6, j = f & 63;
        float val = f2tf32f(vbase[d * HW + j]);
        int fb  = (j >> 3) * 2 + (d >> 4);
        int ln  = (d & 7) * 4 + (j & 3);
        int reg = ((d >> 3) & 1) + 2 * ((j >> 2) & 1);
        Vf[fb * 140 + ln * 4 + reg] = val;
    }
    rs[tid]       = rbase[hw0 + tid];
    rs[tid + 128] = rbase[hw0 + tid + 128];

    const uint4* cf4 = (const uint4*)cf;
    const int nbb = wid * 8;

    float acc[2][8][4] = {};
    float pv[16], pr0, pr1;

    for (int i = 0; i < 64; i++) {
        __syncthreads();
        const int cur = i & 1;
        if (i < 63) {
            const float* vsrc = vbase + (i + 1) * 64;
            #pragma unroll
            for (int q = 0; q < 16; q++) {
                int f = tid + q * 128;
                int d = f >> 6, j = f & 63;
                pv[q] = vsrc[d * HW + j];
            }
            pr0 = rbase[(i + 1) * HW + hw0 + tid];
            pr1 = rbase[(i + 1) * HW + hw0 + tid + 128];
        }
        const uint4* vp4 = (const uint4*)(Vf + cur * FO_VF);
        const float* rr  = rs + cur * FO_RS;

        float t[2][8][4];
        uint4 bv[8];
        #pragma unroll
        for (int jc = 0; jc < 8; jc++) {
            uint4 av0 = vp4[(jc * 2 + 0) * 35 + lane];
            uint4 av1 = vp4[(jc * 2 + 1) * 35 + lane];
            uint32_t a0[4] = {av0.x, av0.y, av0.z, av0.w};
            uint32_t a1[4] = {av1.x, av1.y, av1.z, av1.w};
            if ((jc & 1) == 0) {
                #pragma unroll
                for (int ns = 0; ns < 8; ns++)
                    bv[ns] = cf4[((nbb + ns) * 4 + (jc >> 1)) * 33 + lane];
            }
            #pragma unroll
            for (int ns = 0; ns < 8; ns++) {
                uint32_t b0 = (jc & 1) ? bv[ns].z : bv[ns].x;
                uint32_t b1 = (jc & 1) ? bv[ns].w : bv[ns].y;
                if (jc == 0) {
                    mma16n8k8_z(t[0][ns], a0, b0, b1);
                    mma16n8k8_z(t[1][ns], a1, b0, b1);
                } else {
                    mma16n8k8(t[0][ns], a0, b0, b1);
                    mma16n8k8(t[1][ns], a1, b0, b1);
                }
            }
        }
        #pragma unroll
        for (int ns = 0; ns < 8; ns++) {
            int col0 = wid * 64 + ns * 8 + 2 * kcol;
            float2 rv2 = *(const float2*)&rr[col0];
            #pragma unroll
            for (int ms = 0; ms < 2; ms++) {
                acc[ms][ns][0] += rv2.x * t[ms][ns][0];
                acc[ms][ns][1] += rv2.y * t[ms][ns][1];
                acc[ms][ns][2] += rv2.x * t[ms][ns][2];
                acc[ms][ns][3] += rv2.y * t[ms][ns][3];
            }
        }
        if (i < 63) {
            float* vn = Vf + (1 - cur) * FO_VF;
            float* rn = rs + (1 - cur) * FO_RS;
            #pragma unroll
            for (int q = 0; q < 16; q++) {
                int f = tid + q * 128;
                int d = f >> 6, j = f & 63;
                int fb  = (j >> 3) * 2 + (d >> 4);
                int ln  = (d & 7) * 4 + (j & 3);
                int reg = ((d >> 3) & 1) + 2 * ((j >> 2) & 1);
                vn[fb * 140 + ln * 4 + reg] = f2tf32f(pv[q]);
            }
            rn[tid]       = pr0;
            rn[tid + 128] = pr1;
        }
    }

    float* ob = out + (b * 256 + H * 32) * HW;
    #pragma unroll
    for (int ms = 0; ms < 2; ms++) {
        #pragma unroll
        for (int ns = 0; ns < 8; ns++) {
            int d0  = ms * 16 + mrow;
            int col = hw0 + wid * 64 + ns * 8 + 2 * kcol;
            float2 v0 = *(const float2*)&vbase[d0 * HW + col];
            float2 v1 = *(const float2*)&vbase[(d0 + 8) * HW + col];
            *(float2*)&ob[d0 * HW + col] =
                make_float2(acc[ms][ns][0] + v0.x, acc[ms][ns][1] + v0.y);
            *(float2*)&ob[(d0 + 8) * HW + col] =
                make_float2(acc[ms][ns][2] + v1.x, acc[ms][ns][3] + v1.y);
        }
    }
}

// ---------------------------------------------------------------------------
extern "C" void kernel_launch(void* const* d_in, const int* in_sizes, int n_in,
                              void* d_out, int out_size)
{
    const float* x = (const float*)d_in[0];
    const float* w = (const float*)d_in[1];
    if (n_in >= 2 && in_sizes[0] == 327680 && in_sizes[1] == 2097152) {
        const float* t = x; x = w; w = t;
    }
    float* out = (float*)d_out;

    static int attr_set = 0;
    if (!attr_set) {
        cudaFuncSetAttribute(proj_mma, cudaFuncAttributeMaxDynamicSharedMemorySize,
                             PJ_SMEM_BYTES);
        cudaFuncSetAttribute(row_attn4, cudaFuncAttributeMaxDynamicSharedMemorySize,
                             RA_SMEM_BYTES);
        cudaFuncSetAttribute(fused_out_mma, cudaFuncAttributeMaxDynamicSharedMemorySize,
                             FO_SMEM_BYTES);
        attr_set = 1;
    }

    dim3 g1(32, 10, 2);
    proj_mma<<<g1, 256, PJ_SMEM_BYTES>>>(x, w);

    dim3 g2r(16, 16);
    row_attn4<<<g2r, 256, RA_SMEM_BYTES>>>();
    dim3 g2c(64, 16);
    col_attn_kernel<<<g2c, 256>>>();

    dim3 g4(16, 16);
    fused_out_mma<<<g4, 128, FO_SMEM_BYTES>>>(out);
}

// round 15
// speedup vs baseline: 1.0483x; 1.0136x over previous
#include <cuda_runtime.h>
#include <cstdint>

#define NHh 8
#define Dm 256          // NH*HD
#define OC 1280         // NH*(4*KD+HD)
#define HW 4096
#define NB 2
#define SCALEF 0.17677669529663687f

// Scratch (device globals; no runtime allocation allowed)
__device__ float P_g[NB * OC * HW];            // [b][o][hw]
__device__ float R_g[NB * NHh * 64 * HW];      // [b][H][i][hw] row softmax
__device__ float C_g[NB * NHh * 64 * HW];      // [b][H][j][hw] col softmax

// ---------------------------------------------------------------------------
// helpers
// ---------------------------------------------------------------------------
__device__ __forceinline__ uint32_t f2tf32(float x) {
    uint32_t u;
    asm("cvt.rna.tf32.f32 %0, %1;" : "=r"(u) : "f"(x));
    return u;
}
__device__ __forceinline__ float f2tf32f(float x) {
    uint32_t u = f2tf32(x);
    return __uint_as_float(u);
}
__device__ __forceinline__ void mma16n8k8(float* d, const uint32_t* a,
                                          uint32_t b0, uint32_t b1) {
    asm volatile("mma.sync.aligned.m16n8k8.row.col.f32.tf32.tf32.f32 "
                 "{%0,%1,%2,%3}, {%4,%5,%6,%7}, {%8,%9}, {%0,%1,%2,%3};"
                 : "+f"(d[0]), "+f"(d[1]), "+f"(d[2]), "+f"(d[3])
                 : "r"(a[0]), "r"(a[1]), "r"(a[2]), "r"(a[3]), "r"(b0), "r"(b1));
}
__device__ __forceinline__ void mma16n8k8_z(float* d, const uint32_t* a,
                                            uint32_t b0, uint32_t b1) {
    asm volatile("mma.sync.aligned.m16n8k8.row.col.f32.tf32.tf32.f32 "
                 "{%0,%1,%2,%3}, {%4,%5,%6,%7}, {%8,%9}, {%10,%10,%10,%10};"
                 : "=f"(d[0]), "=f"(d[1]), "=f"(d[2]), "=f"(d[3])
                 : "r"(a[0]), "r"(a[1]), "r"(a[2]), "r"(a[3]), "r"(b0), "r"(b1),
                   "f"(0.0f));
}

// ---------------------------------------------------------------------------
// Kernel 1: projection GEMM (tf32 mma.sync) — R9 proven version.
// ---------------------------------------------------------------------------
#define PJ_AS  (128 * 36)
#define PJ_BS  (32 * 136)
#define PJ_SMEM_FLOATS (2 * PJ_AS + 2 * PJ_BS)
#define PJ_SMEM_BYTES  (PJ_SMEM_FLOATS * 4)

__global__ void __launch_bounds__(256, 2) proj_mma(const float* __restrict__ x,
                                                   const float* __restrict__ w)
{
    extern __shared__ float sm[];
    float* as = sm;
    float* bs = sm + 2 * PJ_AS;

    const int b  = blockIdx.z;
    const int m0 = blockIdx.y * 128;
    const int n0 = blockIdx.x * 128;
    const int tid  = threadIdx.x;
    const int wid  = tid >> 5;
    const int lane = tid & 31;
    const int mrow = lane >> 2;
    const int kcol = lane & 3;
    const int wm = wid & 1;
    const int wn = wid >> 1;
    const float* xb = x + b * (Dm * HW);

    float acc[4][4][4] = {};
    float pa[16], pbr[16];

    #pragma unroll
    for (int q = 0; q < 16; q++) {
        int f = tid + q * 256;
        int o = f >> 5, c = f & 31;
        pa[q]  = w[(m0 + o) * Dm + c];
        int k = f >> 7, n = f & 127;
        pbr[q] = xb[k * HW + n0 + n];
    }
    #pragma unroll
    for (int q = 0; q < 16; q++) {
        int f = tid + q * 256;
        int o = f >> 5, c = f & 31;
        as[o * 36 + c] = f2tf32f(pa[q]);
        int k = f >> 7, n = f & 127;
        bs[k * 136 + n] = f2tf32f(pbr[q]);
    }

    for (int kt = 0; kt < 8; kt++) {
        __syncthreads();
        const int buf = kt & 1;
        if (kt < 7) {
            const int c0 = (kt + 1) * 32;
            #pragma unroll
            for (int q = 0; q < 16; q++) {
                int f = tid + q * 256;
                int o = f >> 5, c = f & 31;
                pa[q]  = w[(m0 + o) * Dm + c0 + c];
                int k = f >> 7, n = f & 127;
                pbr[q] = xb[(c0 + k) * HW + n0 + n];
            }
        }
        const float* ab = as + buf * PJ_AS;
        const float* bb = bs + buf * PJ_BS;
        #pragma unroll
        for (int k8 = 0; k8 < 4; k8++) {
            uint32_t a[4][4];
            #pragma unroll
            for (int msl = 0; msl < 4; msl++) {
                int r0 = wm * 64 + msl * 16 + mrow;
                a[msl][0] = __float_as_uint(ab[r0 * 36 + k8 * 8 + kcol]);
                a[msl][1] = __float_as_uint(ab[(r0 + 8) * 36 + k8 * 8 + kcol]);
                a[msl][2] = __float_as_uint(ab[r0 * 36 + k8 * 8 + 4 + kcol]);
                a[msl][3] = __float_as_uint(ab[(r0 + 8) * 36 + k8 * 8 + 4 + kcol]);
            }
            #pragma unroll
            for (int nsl = 0; nsl < 4; nsl++) {
                int ncol = wn * 32 + nsl * 8 + mrow;
                uint32_t b0 = __float_as_uint(bb[(k8 * 8 + kcol) * 136 + ncol]);
                uint32_t b1 = __float_as_uint(bb[(k8 * 8 + 4 + kcol) * 136 + ncol]);
                #pragma unroll
                for (int msl = 0; msl < 4; msl++)
                    mma16n8k8(acc[msl][nsl], a[msl], b0, b1);
            }
        }
        if (kt < 7) {
            float* an = as + (1 - buf) * PJ_AS;
            float* bn = bs + (1 - buf) * PJ_BS;
            #pragma unroll
            for (int q = 0; q < 16; q++) {
                int f = tid + q * 256;
                int o = f >> 5, c = f & 31;
                an[o * 36 + c] = f2tf32f(pa[q]);
                int k = f >> 7, n = f & 127;
                bn[k * 136 + n] = f2tf32f(pbr[q]);
            }
        }
    }

    float* pb = P_g + b * (OC * HW);
    #pragma unroll
    for (int msl = 0; msl < 4; msl++) {
        #pragma unroll
        for (int nsl = 0; nsl < 4; nsl++) {
            int r0 = m0 + wm * 64 + msl * 16 + mrow;
            int cn = n0 + wn * 32 + nsl * 8 + 2 * kcol;
            *(float2*)&pb[r0 * HW + cn] =
                make_float2(acc[msl][nsl][0], acc[msl][nsl][1]);
            *(float2*)&pb[(r0 + 8) * HW + cn] =
                make_float2(acc[msl][nsl][2], acc[msl][nsl][3]);
        }
    }
}

// ---------------------------------------------------------------------------
// Kernel 2: row attention, w-quad version (unchanged)
// ---------------------------------------------------------------------------
#define QSTR (32 * 65 + 1)
#define ASTR (64 * 65 + 1)
#define RA_SMEM_FLOATS (8 * QSTR)
#define RA_SMEM_BYTES  (RA_SMEM_FLOATS * 4)

__global__ void __launch_bounds__(256) row_attn4()
{
    extern __shared__ float smb[];
    float* q_s = smb;
    float* k_s = smb + 4 * QSTR;

    const int w0 = blockIdx.x * 4;
    const int bh = blockIdx.y;
    const int b  = bh >> 3, H = bh & 7;
    const float* qb = P_g + (b * OC + H * 160) * HW;
    const float* kb = qb + 32 * HW;
    const int tid = threadIdx.x;

    for (int e = tid; e < 8192; e += 256) {
        int ww = e & 3, i = (e >> 2) & 63, d = e >> 8;
        q_s[ww * QSTR + d * 65 + i] = qb[d * HW + i * 64 + w0 + ww];
        k_s[ww * QSTR + d * 65 + i] = kb[d * HW + i * 64 + w0 + ww];
    }
    __syncthreads();

    const int ww = tid >> 6;
    const int gt = tid & 63;
    const int ti = (gt >> 3) * 8;
    const int tj = (gt & 7) * 8;
    const float* qq = q_s + ww * QSTR;
    const float* kk = k_s + ww * QSTR;

    float acc[8][8] = {};
    #pragma unroll 4
    for (int d = 0; d < 32; d++) {
        float qv[8], kv[8];
        #pragma unroll
        for (int u = 0; u < 8; u++) qv[u] = qq[d * 65 + ti + u];
        #pragma unroll
        for (int v = 0; v < 8; v++) kv[v] = kk[d * 65 + tj + v];
        #pragma unroll
        for (int u = 0; u < 8; u++)
            #pragma unroll
            for (int v = 0; v < 8; v++)
                acc[u][v] += qv[u] * kv[v];
    }
    __syncthreads();

    float* a_s = smb;
    #pragma unroll
    for (int u = 0; u < 8; u++)
        #pragma unroll
        for (int v = 0; v < 8; v++)
            a_s[ww * ASTR + (ti + u) * 65 + (tj + v)] = acc[u][v] * SCALEF;
    __syncthreads();

    {
        const int ww2 = tid & 3;
        const int j   = tid >> 2;
        float* col = a_s + ww2 * ASTR + j;
        float mx = -1e30f;
        #pragma unroll 8
        for (int i = 0; i < 64; i++) mx = fmaxf(mx, col[i * 65]);
        float s = 0.f;
        #pragma unroll 8
        for (int i = 0; i < 64; i++) {
            float e = __expf(col[i * 65] - mx);
            col[i * 65] = e;
            s += e;
        }
        float inv = 1.f / s;
        float* rb = R_g + bh * (64 * HW) + j * 64 + w0 + ww2;
        #pragma unroll 8
        for (int i = 0; i < 64; i++)
            rb[i * HW] = col[i * 65] * inv;
    }
}

// ---------------------------------------------------------------------------
// Kernel 3: column attention — parallel softmax (kept)
// ---------------------------------------------------------------------------
__global__ void col_attn_kernel()
{
    int h  = blockIdx.x;
    int bh = blockIdx.y;
    int b  = bh >> 3, H = bh & 7;
    const float* base = P_g + (b * OC + H * 160) * HW;
    int tid = threadIdx.x;

    __shared__ float q_s[32][64];
    __shared__ float k_s[32][64];
    __shared__ float a_s[64][68];

    for (int f = tid; f < 2048; f += 256) {
        int d = f >> 6, i = f & 63;
        q_s[d][i] = base[(64 + d) * HW + h * 64 + i];
        k_s[d][i] = base[(96 + d) * HW + h * 64 + i];
    }
    __syncthreads();

    int ti = (tid >> 4) * 4;
    int tj = (tid & 15) * 4;
    float acc[4][4] = {};
    #pragma unroll
    for (int d = 0; d < 32; d++) {
        float4 av = *(const float4*)&q_s[d][ti];
        float4 bv = *(const float4*)&k_s[d][tj];
        float avv[4] = {av.x, av.y, av.z, av.w};
        float bvv[4] = {bv.x, bv.y, bv.z, bv.w};
        #pragma unroll
        for (int u = 0; u < 4; u++)
            #pragma unroll
            for (int v2 = 0; v2 < 4; v2++)
                acc[u][v2] += avv[u] * bvv[v2];
    }
    #pragma unroll
    for (int u = 0; u < 4; u++)
        #pragma unroll
        for (int v2 = 0; v2 < 4; v2++)
            a_s[ti + u][tj + v2] = acc[u][v2] * SCALEF;
    __syncthreads();

    {
        float* pm = (float*)q_s;
        float* ps = pm + 4 * 65;
        const int j = tid & 63;
        const int p = tid >> 6;
        float mx = -1e30f;
        #pragma unroll
        for (int u = 0; u < 16; u++) mx = fmaxf(mx, a_s[p * 16 + u][j]);
        pm[p * 65 + j] = mx;
        __syncthreads();
        float m4 = fmaxf(fmaxf(pm[j], pm[65 + j]), fmaxf(pm[130 + j], pm[195 + j]));
        float s = 0.f;
        #pragma unroll
        for (int u = 0; u < 16; u++) {
            float e = __expf(a_s[p * 16 + u][j] - m4);
            a_s[p * 16 + u][j] = e;
            s += e;
        }
        ps[p * 65 + j] = s;
        __syncthreads();
        float tot = ps[j] + ps[65 + j] + ps[130 + j] + ps[195 + j];
        float inv = 1.f / tot;
        float* cb = C_g + bh * (64 * HW) + h * 64 + j;
        #pragma unroll
        for (int u = 0; u < 16; u++)
            cb[(p * 16 + u) * HW] = a_s[p * 16 + u][j] * inv;
    }
}

// ---------------------------------------------------------------------------
// Kernel 4: fused output — register-resident c, 8 thin warps, in-kernel
// double-buffered V staging + smem r.
// CTA: 256 threads / 8 warps / hw-tile 128.  Warp = (msw d-half) x (q hw-qtr).
//   per i:  t = V_i(msw) @ c(regs);  acc += r o t;  out = acc + v
// ---------------------------------------------------------------------------
#define FO_VP  2240                       // V fragment panel floats
#define FO_SMEM_FLOATS 8448               // c scatter area; reused for V+r
#define FO_SMEM_BYTES (FO_SMEM_FLOATS * 4)  // 33792 B

__global__ void __launch_bounds__(256, 2) fused_out_mma(float* __restrict__ out)
{
    extern __shared__ float sm[];
    float* Vf = sm;                       // [2][FO_VP] (after phase 1)
    float* rs = sm + 2 * FO_VP;           // [2][128]

    const int hw0 = blockIdx.x * 128;
    const int bh  = blockIdx.y;
    const int b   = bh >> 3, H = bh & 7;
    const float* vbase = P_g + (b * OC + H * 160 + 128) * HW;
    const float* rbase = R_g + bh * (64 * HW);
    const float* cbase = C_g + bh * (64 * HW);
    const int tid  = threadIdx.x;
    const int wid  = tid >> 5;
    const int lane = tid & 31;
    const int mrow = lane >> 2;
    const int kcol = lane & 3;
    const int msw  = wid >> 2;    // d half
    const int q    = wid & 3;     // hw quarter

    // Phase 1: scatter c fragments into smem, load to registers.
    for (int f = tid; f < 8192; f += 256) {
        int j = f >> 7, m = f & 127;
        int nb  = m >> 3;
        int jcp = j >> 4;
        int ln  = (m & 7) * 4 + (j & 3);
        int reg = ((j >> 3) & 1) * 2 + ((j >> 2) & 1);
        sm[(nb * 4 + jcp) * 132 + ln * 4 + reg] = f2tf32f(cbase[j * HW + hw0 + m]);
    }
    __syncthreads();
    uint4 cq[4][4];
    {
        const uint4* cf4 = (const uint4*)sm;
        #pragma unroll
        for (int ns = 0; ns < 4; ns++)
            #pragma unroll
            for (int jcp = 0; jcp < 4; jcp++)
                cq[ns][jcp] = cf4[((q * 4 + ns) * 4 + jcp) * 33 + lane];
    }
    __syncthreads();

    // stage i = 0 panel + r into buffer 0
    #pragma unroll
    for (int q2 = 0; q2 < 8; q2++) {
        int f = tid + q2 * 256;
        int d = f >> 6, j = f & 63;
        float val = f2tf32f(vbase[d * HW + j]);
        int fb  = (j >> 3) * 2 + (d >> 4);
        int ln  = (d & 7) * 4 + (j & 3);
        int reg = ((d >> 3) & 1) + 2 * ((j >> 2) & 1);
        Vf[fb * 140 + ln * 4 + reg] = val;
    }
    if (tid < 128) rs[tid] = rbase[hw0 + tid];
    __syncthreads();

    float acc[4][4] = {};
    float pv[8], pr = 0.f;

    for (int i = 0; i < 64; i++) {
        const int cur = i & 1;
        if (i < 63) {
            const float* vsrc = vbase + (i + 1) * 64;
            #pragma unroll
            for (int q2 = 0; q2 < 8; q2++) {
                int f = tid + q2 * 256;
                pv[q2] = vsrc[(f >> 6) * HW + (f & 63)];
            }
            if (tid < 128) pr = rbase[(i + 1) * HW + hw0 + tid];
        }
        const uint4* vp4 = (const uint4*)(Vf + cur * FO_VP);
        const float* rr  = rs + cur * 128;

        float t[4][4];
        #pragma unroll
        for (int jc = 0; jc < 8; jc++) {
            uint4 av = vp4[(jc * 2 + msw) * 35 + lane];
            uint32_t a[4] = {av.x, av.y, av.z, av.w};
            #pragma unroll
            for (int ns = 0; ns < 4; ns++) {
                uint32_t b0 = (jc & 1) ? cq[ns][jc >> 1].z : cq[ns][jc >> 1].x;
                uint32_t b1 = (jc & 1) ? cq[ns][jc >> 1].w : cq[ns][jc >> 1].y;
                if (jc == 0) mma16n8k8_z(t[ns], a, b0, b1);
                else         mma16n8k8(t[ns], a, b0, b1);
            }
        }
        #pragma unroll
        for (int ns = 0; ns < 4; ns++) {
            int col0 = q * 32 + ns * 8 + 2 * kcol;
            float2 rv2 = *(const float2*)&rr[col0];
            acc[ns][0] += rv2.x * t[ns][0];
            acc[ns][1] += rv2.y * t[ns][1];
            acc[ns][2] += rv2.x * t[ns][2];
            acc[ns][3] += rv2.y * t[ns][3];
        }
        if (i < 63) {
            float* vn = Vf + (1 - cur) * FO_VP;
            #pragma unroll
            for (int q2 = 0; q2 < 8; q2++) {
                int f = tid + q2 * 256;
                int d = f >> 6, j = f & 63;
                int fb  = (j >> 3) * 2 + (d >> 4);
                int ln  = (d & 7) * 4 + (j & 3);
                int reg = ((d >> 3) & 1) + 2 * ((j >> 2) & 1);
                vn[fb * 140 + ln * 4 + reg] = f2tf32f(pv[q2]);
            }
            if (tid < 128) rs[(1 - cur) * 128 + tid] = pr;
        }
        __syncthreads();
    }

    // epilogue: out[d][hw] = acc + v
    const int d0 = msw * 16 + mrow;
    float* ob = out + (b * 256 + H * 32) * HW;
    #pragma unroll
    for (int ns = 0; ns < 4; ns++) {
        int col = hw0 + q * 32 + ns * 8 + 2 * kcol;
        float2 v0 = *(const float2*)&vbase[d0 * HW + col];
        float2 v1 = *(const float2*)&vbase[(d0 + 8) * HW + col];
        *(float2*)&ob[d0 * HW + col] =
            make_float2(acc[ns][0] + v0.x, acc[ns][1] + v0.y);
        *(float2*)&ob[(d0 + 8) * HW + col] =
            make_float2(acc[ns][2] + v1.x, acc[ns][3] + v1.y);
    }
}

// ---------------------------------------------------------------------------
extern "C" void kernel_launch(void* const* d_in, const int* in_sizes, int n_in,
                              void* d_out, int out_size)
{
    const float* x = (const float*)d_in[0];
    const float* w = (const float*)d_in[1];
    if (n_in >= 2 && in_sizes[0] == 327680 && in_sizes[1] == 2097152) {
        const float* t = x; x = w; w = t;
    }
    float* out = (float*)d_out;

    static int attr_set = 0;
    if (!attr_set) {
        cudaFuncSetAttribute(proj_mma, cudaFuncAttributeMaxDynamicSharedMemorySize,
                             PJ_SMEM_BYTES);
        cudaFuncSetAttribute(row_attn4, cudaFuncAttributeMaxDynamicSharedMemorySize,
                             RA_SMEM_BYTES);
        cudaFuncSetAttribute(fused_out_mma, cudaFuncAttributeMaxDynamicSharedMemorySize,
                             FO_SMEM_BYTES);
        attr_set = 1;
    }

    dim3 g1(32, 10, 2);
    proj_mma<<<g1, 256, PJ_SMEM_BYTES>>>(x, w);

    dim3 g2r(16, 16);
    row_attn4<<<g2r, 256, RA_SMEM_BYTES>>>();
    dim3 g2c(64, 16);
    col_attn_kernel<<<g2c, 256>>>();

    dim3 g4(32, 16);
    fused_out_mma<<<g4, 256, FO_SMEM_BYTES>>>(out);
}

// round 16
// speedup vs baseline: 1.0603x; 1.0115x over previous
#include <cuda_runtime.h>
#include <cstdint>

#define NHh 8
#define Dm 256          // NH*HD
#define OC 1280         // NH*(4*KD+HD)
#define HW 4096
#define NB 2
#define SCALEF 0.17677669529663687f

// Scratch (device globals; no runtime allocation allowed)
__device__ float P_g[NB * OC * HW];            // [b][o][hw]
__device__ float R_g[NB * NHh * 64 * HW];      // [b][H][i][hw] row softmax
__device__ float C_g[NB * NHh * 64 * HW];      // [b][H][j][hw] col softmax

// ---------------------------------------------------------------------------
// helpers
// ---------------------------------------------------------------------------
__device__ __forceinline__ uint32_t f2tf32(float x) {
    uint32_t u;
    asm("cvt.rna.tf32.f32 %0, %1;" : "=r"(u) : "f"(x));
    return u;
}
__device__ __forceinline__ float f2tf32f(float x) {
    uint32_t u = f2tf32(x);
    return __uint_as_float(u);
}
__device__ __forceinline__ void mma16n8k8(float* d, const uint32_t* a,
                                          uint32_t b0, uint32_t b1) {
    asm volatile("mma.sync.aligned.m16n8k8.row.col.f32.tf32.tf32.f32 "
                 "{%0,%1,%2,%3}, {%4,%5,%6,%7}, {%8,%9}, {%0,%1,%2,%3};"
                 : "+f"(d[0]), "+f"(d[1]), "+f"(d[2]), "+f"(d[3])
                 : "r"(a[0]), "r"(a[1]), "r"(a[2]), "r"(a[3]), "r"(b0), "r"(b1));
}
__device__ __forceinline__ void mma16n8k8_z(float* d, const uint32_t* a,
                                            uint32_t b0, uint32_t b1) {
    asm volatile("mma.sync.aligned.m16n8k8.row.col.f32.tf32.tf32.f32 "
                 "{%0,%1,%2,%3}, {%4,%5,%6,%7}, {%8,%9}, {%10,%10,%10,%10};"
                 : "=f"(d[0]), "=f"(d[1]), "=f"(d[2]), "=f"(d[3])
                 : "r"(a[0]), "r"(a[1]), "r"(a[2]), "r"(a[3]), "r"(b0), "r"(b1),
                   "f"(0.0f));
}

// ---------------------------------------------------------------------------
// Kernel 1: projection GEMM (tf32 mma.sync) — R9 proven version.
// ---------------------------------------------------------------------------
#define PJ_AS  (128 * 36)
#define PJ_BS  (32 * 136)
#define PJ_SMEM_FLOATS (2 * PJ_AS + 2 * PJ_BS)
#define PJ_SMEM_BYTES  (PJ_SMEM_FLOATS * 4)

__global__ void __launch_bounds__(256, 2) proj_mma(const float* __restrict__ x,
                                                   const float* __restrict__ w)
{
    extern __shared__ float sm[];
    float* as = sm;
    float* bs = sm + 2 * PJ_AS;

    const int b  = blockIdx.z;
    const int m0 = blockIdx.y * 128;
    const int n0 = blockIdx.x * 128;
    const int tid  = threadIdx.x;
    const int wid  = tid >> 5;
    const int lane = tid & 31;
    const int mrow = lane >> 2;
    const int kcol = lane & 3;
    const int wm = wid & 1;
    const int wn = wid >> 1;
    const float* xb = x + b * (Dm * HW);

    float acc[4][4][4] = {};
    float pa[16], pbr[16];

    #pragma unroll
    for (int q = 0; q < 16; q++) {
        int f = tid + q * 256;
        int o = f >> 5, c = f & 31;
        pa[q]  = w[(m0 + o) * Dm + c];
        int k = f >> 7, n = f & 127;
        pbr[q] = xb[k * HW + n0 + n];
    }
    #pragma unroll
    for (int q = 0; q < 16; q++) {
        int f = tid + q * 256;
        int o = f >> 5, c = f & 31;
        as[o * 36 + c] = f2tf32f(pa[q]);
        int k = f >> 7, n = f & 127;
        bs[k * 136 + n] = f2tf32f(pbr[q]);
    }

    for (int kt = 0; kt < 8; kt++) {
        __syncthreads();
        const int buf = kt & 1;
        if (kt < 7) {
            const int c0 = (kt + 1) * 32;
            #pragma unroll
            for (int q = 0; q < 16; q++) {
                int f = tid + q * 256;
                int o = f >> 5, c = f & 31;
                pa[q]  = w[(m0 + o) * Dm + c0 + c];
                int k = f >> 7, n = f & 127;
                pbr[q] = xb[(c0 + k) * HW + n0 + n];
            }
        }
        const float* ab = as + buf * PJ_AS;
        const float* bb = bs + buf * PJ_BS;
        #pragma unroll
        for (int k8 = 0; k8 < 4; k8++) {
            uint32_t a[4][4];
            #pragma unroll
            for (int msl = 0; msl < 4; msl++) {
                int r0 = wm * 64 + msl * 16 + mrow;
                a[msl][0] = __float_as_uint(ab[r0 * 36 + k8 * 8 + kcol]);
                a[msl][1] = __float_as_uint(ab[(r0 + 8) * 36 + k8 * 8 + kcol]);
                a[msl][2] = __float_as_uint(ab[r0 * 36 + k8 * 8 + 4 + kcol]);
                a[msl][3] = __float_as_uint(ab[(r0 + 8) * 36 + k8 * 8 + 4 + kcol]);
            }
            #pragma unroll
            for (int nsl = 0; nsl < 4; nsl++) {
                int ncol = wn * 32 + nsl * 8 + mrow;
                uint32_t b0 = __float_as_uint(bb[(k8 * 8 + kcol) * 136 + ncol]);
                uint32_t b1 = __float_as_uint(bb[(k8 * 8 + 4 + kcol) * 136 + ncol]);
                #pragma unroll
                for (int msl = 0; msl < 4; msl++)
                    mma16n8k8(acc[msl][nsl], a[msl], b0, b1);
            }
        }
        if (kt < 7) {
            float* an = as + (1 - buf) * PJ_AS;
            float* bn = bs + (1 - buf) * PJ_BS;
            #pragma unroll
            for (int q = 0; q < 16; q++) {
                int f = tid + q * 256;
                int o = f >> 5, c = f & 31;
                an[o * 36 + c] = f2tf32f(pa[q]);
                int k = f >> 7, n = f & 127;
                bn[k * 136 + n] = f2tf32f(pbr[q]);
            }
        }
    }

    float* pb = P_g + b * (OC * HW);
    #pragma unroll
    for (int msl = 0; msl < 4; msl++) {
        #pragma unroll
        for (int nsl = 0; nsl < 4; nsl++) {
            int r0 = m0 + wm * 64 + msl * 16 + mrow;
            int cn = n0 + wn * 32 + nsl * 8 + 2 * kcol;
            *(float2*)&pb[r0 * HW + cn] =
                make_float2(acc[msl][nsl][0], acc[msl][nsl][1]);
            *(float2*)&pb[(r0 + 8) * HW + cn] =
                make_float2(acc[msl][nsl][2], acc[msl][nsl][3]);
        }
    }
}

// ---------------------------------------------------------------------------
// Kernel 2: MERGED row + col attention in one launch.
// grid.x = 80: blocks [0,16) = row path (w-quad), [16,80) = col path (one h).
// Both use 256 threads; dynamic smem = RA size (row needs 66.6KB).
// ---------------------------------------------------------------------------
#define QSTR (32 * 65 + 1)
#define ASTR (64 * 65 + 1)
#define RA_SMEM_FLOATS (8 * QSTR)
#define RA_SMEM_BYTES  (RA_SMEM_FLOATS * 4)

__global__ void __launch_bounds__(256) attn_kernel()
{
    extern __shared__ float smb[];
    const int bh = blockIdx.y;
    const int b  = bh >> 3, H = bh & 7;
    const int tid = threadIdx.x;

    if (blockIdx.x < 16) {
        // ---------------- row path (w-quad) ----------------
        float* q_s = smb;
        float* k_s = smb + 4 * QSTR;

        const int w0 = blockIdx.x * 4;
        const float* qb = P_g + (b * OC + H * 160) * HW;
        const float* kb = qb + 32 * HW;

        for (int e = tid; e < 8192; e += 256) {
            int ww = e & 3, i = (e >> 2) & 63, d = e >> 8;
            q_s[ww * QSTR + d * 65 + i] = qb[d * HW + i * 64 + w0 + ww];
            k_s[ww * QSTR + d * 65 + i] = kb[d * HW + i * 64 + w0 + ww];
        }
        __syncthreads();

        const int ww = tid >> 6;
        const int gt = tid & 63;
        const int ti = (gt >> 3) * 8;
        const int tj = (gt & 7) * 8;
        const float* qq = q_s + ww * QSTR;
        const float* kk = k_s + ww * QSTR;

        float acc[8][8] = {};
        #pragma unroll 4
        for (int d = 0; d < 32; d++) {
            float qv[8], kv[8];
            #pragma unroll
            for (int u = 0; u < 8; u++) qv[u] = qq[d * 65 + ti + u];
            #pragma unroll
            for (int v = 0; v < 8; v++) kv[v] = kk[d * 65 + tj + v];
            #pragma unroll
            for (int u = 0; u < 8; u++)
                #pragma unroll
                for (int v = 0; v < 8; v++)
                    acc[u][v] += qv[u] * kv[v];
        }
        __syncthreads();

        float* a_s = smb;
        #pragma unroll
        for (int u = 0; u < 8; u++)
            #pragma unroll
            for (int v = 0; v < 8; v++)
                a_s[ww * ASTR + (ti + u) * 65 + (tj + v)] = acc[u][v] * SCALEF;
        __syncthreads();

        {
            const int ww2 = tid & 3;
            const int j   = tid >> 2;
            float* col = a_s + ww2 * ASTR + j;
            float mx = -1e30f;
            #pragma unroll 8
            for (int i = 0; i < 64; i++) mx = fmaxf(mx, col[i * 65]);
            float s = 0.f;
            #pragma unroll 8
            for (int i = 0; i < 64; i++) {
                float e = __expf(col[i * 65] - mx);
                col[i * 65] = e;
                s += e;
            }
            float inv = 1.f / s;
            float* rb = R_g + bh * (64 * HW) + j * 64 + w0 + ww2;
            #pragma unroll 8
            for (int i = 0; i < 64; i++)
                rb[i * HW] = col[i * 65] * inv;
        }
    } else {
        // ---------------- col path (one h) ----------------
        float* q_s = smb;                 // [32][64]
        float* k_s = smb + 2048;          // [32][64]
        float* a_s = smb + 4096;          // [64][68]

        const int h = blockIdx.x - 16;
        const float* base = P_g + (b * OC + H * 160) * HW;

        for (int f = tid; f < 2048; f += 256) {
            int d = f >> 6, i = f & 63;
            q_s[d * 64 + i] = base[(64 + d) * HW + h * 64 + i];
            k_s[d * 64 + i] = base[(96 + d) * HW + h * 64 + i];
        }
        __syncthreads();

        int ti = (tid >> 4) * 4;
        int tj = (tid & 15) * 4;
        float acc[4][4] = {};
        #pragma unroll
        for (int d = 0; d < 32; d++) {
            float4 av = *(const float4*)&q_s[d * 64 + ti];
            float4 bv = *(const float4*)&k_s[d * 64 + tj];
            float avv[4] = {av.x, av.y, av.z, av.w};
            float bvv[4] = {bv.x, bv.y, bv.z, bv.w};
            #pragma unroll
            for (int u = 0; u < 4; u++)
                #pragma unroll
                for (int v2 = 0; v2 < 4; v2++)
                    acc[u][v2] += avv[u] * bvv[v2];
        }
        #pragma unroll
        for (int u = 0; u < 4; u++)
            #pragma unroll
            for (int v2 = 0; v2 < 4; v2++)
                a_s[(ti + u) * 68 + tj + v2] = acc[u][v2] * SCALEF;
        __syncthreads();

        {
            float* pm = q_s;              // reuse
            float* ps = pm + 4 * 65;
            const int j = tid & 63;
            const int p = tid >> 6;
            float mx = -1e30f;
            #pragma unroll
            for (int u = 0; u < 16; u++) mx = fmaxf(mx, a_s[(p * 16 + u) * 68 + j]);
            pm[p * 65 + j] = mx;
            __syncthreads();
            float m4 = fmaxf(fmaxf(pm[j], pm[65 + j]), fmaxf(pm[130 + j], pm[195 + j]));
            float s = 0.f;
            #pragma unroll
            for (int u = 0; u < 16; u++) {
                float e = __expf(a_s[(p * 16 + u) * 68 + j] - m4);
                a_s[(p * 16 + u) * 68 + j] = e;
                s += e;
            }
            ps[p * 65 + j] = s;
            __syncthreads();
            float tot = ps[j] + ps[65 + j] + ps[130 + j] + ps[195 + j];
            float inv = 1.f / tot;
            float* cb = C_g + bh * (64 * HW) + h * 64 + j;
            #pragma unroll
            for (int u = 0; u < 16; u++)
                cb[(p * 16 + u) * HW] = a_s[(p * 16 + u) * 68 + j] * inv;
        }
    }
}

// ---------------------------------------------------------------------------
// Kernel 4: fused output — R9-EXACT version (117.8us, proven twice).
// Wide warps (64 hw per warp); CTA 128 threads / 4 warps / 256 hw tile.
// ---------------------------------------------------------------------------
#define FO_CF   (128 * 132)
#define FO_VF   (16 * 140)
#define FO_RS   256
#define FO_SMEM_FLOATS (FO_CF + 2 * FO_VF + 2 * FO_RS)
#define FO_SMEM_BYTES  (FO_SMEM_FLOATS * 4)   // 87552 B -> 2 CTA/SM

__global__ void __launch_bounds__(128, 2) fused_out_mma(float* __restrict__ out)
{
    extern __shared__ float sm[];
    float* cf = sm;
    float* Vf = sm + FO_CF;
    float* rs = sm + FO_CF + 2 * FO_VF;

    const int hw0 = blockIdx.x * 256;
    const int bh  = blockIdx.y;
    const int b   = bh >> 3, H = bh & 7;
    const float* vbase = P_g + (b * OC + H * 160 + 128) * HW;
    const float* rbase = R_g + bh * (64 * HW);
    const float* cbase = C_g + bh * (64 * HW);
    const int tid  = threadIdx.x;
    const int wid  = tid >> 5;
    const int lane = tid & 31;
    const int mrow = lane >> 2;
    const int kcol = lane & 3;

    for (int f = tid; f < 16384; f += 128) {
        int j = f >> 8, m = f & 255;
        int nb   = m >> 3;
        int jcp  = j >> 4;
        int ln   = (m & 7) * 4 + (j & 3);
        int reg  = ((j >> 3) & 1) * 2 + ((j >> 2) & 1);
        cf[(nb * 4 + jcp) * 132 + ln * 4 + reg] = f2tf32f(cbase[j * HW + hw0 + m]);
    }
    #pragma unroll
    for (int q = 0; q < 16; q++) {
        int f = tid + q * 128;
        int d = f >> 6, j = f & 63;
        float val = f2tf32f(vbase[d * HW + j]);
        int fb  = (j >> 3) * 2 + (d >> 4);
        int ln  = (d & 7) * 4 + (j & 3);
        int reg = ((d >> 3) & 1) + 2 * ((j >> 2) & 1);
        Vf[fb * 140 + ln * 4 + reg] = val;
    }
    rs[tid]       = rbase[hw0 + tid];
    rs[tid + 128] = rbase[hw0 + tid + 128];

    const uint4* cf4 = (const uint4*)cf;
    const int nbb = wid * 8;

    float acc[2][8][4] = {};
    float pv[16], pr0, pr1;

    for (int i = 0; i < 64; i++) {
        __syncthreads();
        const int cur = i & 1;
        if (i < 63) {
            const float* vsrc = vbase + (i + 1) * 64;
            #pragma unroll
            for (int q = 0; q < 16; q++) {
                int f = tid + q * 128;
                int d = f >> 6, j = f & 63;
                pv[q] = vsrc[d * HW + j];
            }
            pr0 = rbase[(i + 1) * HW + hw0 + tid];
            pr1 = rbase[(i + 1) * HW + hw0 + tid + 128];
        }
        const uint4* vp4 = (const uint4*)(Vf + cur * FO_VF);
        const float* rr  = rs + cur * FO_RS;

        float t[2][8][4];
        uint4 bv[8];
        #pragma unroll
        for (int jc = 0; jc < 8; jc++) {
            uint4 av0 = vp4[(jc * 2 + 0) * 35 + lane];
            uint4 av1 = vp4[(jc * 2 + 1) * 35 + lane];
            uint32_t a0[4] = {av0.x, av0.y, av0.z, av0.w};
            uint32_t a1[4] = {av1.x, av1.y, av1.z, av1.w};
            if ((jc & 1) == 0) {
                #pragma unroll
                for (int ns = 0; ns < 8; ns++)
                    bv[ns] = cf4[((nbb + ns) * 4 + (jc >> 1)) * 33 + lane];
            }
            #pragma unroll
            for (int ns = 0; ns < 8; ns++) {
                uint32_t b0 = (jc & 1) ? bv[ns].z : bv[ns].x;
                uint32_t b1 = (jc & 1) ? bv[ns].w : bv[ns].y;
                if (jc == 0) {
                    mma16n8k8_z(t[0][ns], a0, b0, b1);
                    mma16n8k8_z(t[1][ns], a1, b0, b1);
                } else {
                    mma16n8k8(t[0][ns], a0, b0, b1);
                    mma16n8k8(t[1][ns], a1, b0, b1);
                }
            }
        }
        #pragma unroll
        for (int ns = 0; ns < 8; ns++) {
            int col0 = wid * 64 + ns * 8 + 2 * kcol;
            float2 rv2 = *(const float2*)&rr[col0];
            #pragma unroll
            for (int ms = 0; ms < 2; ms++) {
                acc[ms][ns][0] += rv2.x * t[ms][ns][0];
                acc[ms][ns][1] += rv2.y * t[ms][ns][1];
                acc[ms][ns][2] += rv2.x * t[ms][ns][2];
                acc[ms][ns][3] += rv2.y * t[ms][ns][3];
            }
        }
        if (i < 63) {
            float* vn = Vf + (1 - cur) * FO_VF;
            float* rn = rs + (1 - cur) * FO_RS;
            #pragma unroll
            for (int q = 0; q < 16; q++) {
                int f = tid + q * 128;
                int d = f >> 6, j = f & 63;
                int fb  = (j >> 3) * 2 + (d >> 4);
                int ln  = (d & 7) * 4 + (j & 3);
                int reg = ((d >> 3) & 1) + 2 * ((j >> 2) & 1);
                vn[fb * 140 + ln * 4 + reg] = f2tf32f(pv[q]);
            }
            rn[tid]       = pr0;
            rn[tid + 128] = pr1;
        }
    }

    float* ob = out + (b * 256 + H * 32) * HW;
    #pragma unroll
    for (int ms = 0; ms < 2; ms++) {
        #pragma unroll
        for (int ns = 0; ns < 8; ns++) {
            int d0  = ms * 16 + mrow;
            int col = hw0 + wid * 64 + ns * 8 + 2 * kcol;
            float2 v0 = *(const float2*)&vbase[d0 * HW + col];
            float2 v1 = *(const float2*)&vbase[(d0 + 8) * HW + col];
            *(float2*)&ob[d0 * HW + col] =
                make_float2(acc[ms][ns][0] + v0.x, acc[ms][ns][1] + v0.y);
            *(float2*)&ob[(d0 + 8) * HW + col] =
                make_float2(acc[ms][ns][2] + v1.x, acc[ms][ns][3] + v1.y);
        }
    }
}

// ---------------------------------------------------------------------------
extern "C" void kernel_launch(void* const* d_in, const int* in_sizes, int n_in,
                              void* d_out, int out_size)
{
    const float* x = (const float*)d_in[0];
    const float* w = (const float*)d_in[1];
    if (n_in >= 2 && in_sizes[0] == 327680 && in_sizes[1] == 2097152) {
        const float* t = x; x = w; w = t;
    }
    float* out = (float*)d_out;

    static int attr_set = 0;
    if (!attr_set) {
        cudaFuncSetAttribute(proj_mma, cudaFuncAttributeMaxDynamicSharedMemorySize,
                             PJ_SMEM_BYTES);
        cudaFuncSetAttribute(attn_kernel, cudaFuncAttributeMaxDynamicSharedMemorySize,
                             RA_SMEM_BYTES);
        cudaFuncSetAttribute(fused_out_mma, cudaFuncAttributeMaxDynamicSharedMemorySize,
                             FO_SMEM_BYTES);
        attr_set = 1;
    }

    dim3 g1(32, 10, 2);
    proj_mma<<<g1, 256, PJ_SMEM_BYTES>>>(x, w);

    dim3 g2(80, 16);
    attn_kernel<<<g2, 256, RA_SMEM_BYTES>>>();

    dim3 g4(16, 16);
    fused_out_mma<<<g4, 128, FO_SMEM_BYTES>>>(out);
}